// round 5
// baseline (speedup 1.0000x reference)
#include <cuda_runtime.h>
#include <math.h>

#define LEVELS 16
#define TABLE_SIZE 524288
#define HMASK (TABLE_SIZE - 1)
#define NPTS 1048576
#define PRIME 2654435761u
#define THREADS 256
#define NBUCKETS 65536           // 256 x 256 Morton buckets, ~16 pts each
#define SCAN_BLK 1024
#define NSCANBLK (NBUCKETS / SCAN_BLK)   // 64
#define CACHE_ENT 1536           // smem table-cache entries (float2)

struct ResArr { float r[LEVELS]; };

// Scratch (__device__ globals: the sanctioned no-allocation path)
__device__ int    d_hist[NBUCKETS];
__device__ int    d_offs[NBUCKETS];
__device__ int    d_bsum[NSCANBLK];
__device__ int    d_bbase[NSCANBLK];
__device__ float4 d_pts[NPTS];   // (x, y, bitcast(orig index), pad)

__device__ __forceinline__ unsigned expand8(unsigned v) {
    v = (v | (v << 4)) & 0x0F0Fu;
    v = (v | (v << 2)) & 0x3333u;
    v = (v | (v << 1)) & 0x5555u;
    return v;
}
__device__ __forceinline__ unsigned bucket_of(float2 p) {
    unsigned bx = (unsigned)(int)(p.x * 256.0f);
    unsigned by = (unsigned)(int)(p.y * 256.0f);
    bx = bx > 255u ? 255u : bx;
    by = by > 255u ? 255u : by;
    return expand8(bx) | (expand8(by) << 1);
}

__global__ void zero_hist_kernel() {
    int i = blockIdx.x * blockDim.x + threadIdx.x;
    d_hist[i] = 0;
}

__global__ __launch_bounds__(THREADS)
void hist_kernel(const float2* __restrict__ x) {
    int i = blockIdx.x * blockDim.x + threadIdx.x;
    atomicAdd(&d_hist[bucket_of(x[i])], 1);
}

__global__ __launch_bounds__(SCAN_BLK)
void scan1_kernel() {
    __shared__ int sm[SCAN_BLK];
    int t = threadIdx.x;
    int i = blockIdx.x * SCAN_BLK + t;
    int v = d_hist[i];
    sm[t] = v;
    __syncthreads();
    for (int off = 1; off < SCAN_BLK; off <<= 1) {
        int u = (t >= off) ? sm[t - off] : 0;
        __syncthreads();
        sm[t] += u;
        __syncthreads();
    }
    int incl = sm[t];
    d_offs[i] = incl - v;
    if (t == SCAN_BLK - 1) d_bsum[blockIdx.x] = incl;
}

__global__ void scan2_kernel() {
    __shared__ int sm[NSCANBLK];
    int t = threadIdx.x;
    int v = d_bsum[t];
    sm[t] = v;
    __syncthreads();
    for (int off = 1; off < NSCANBLK; off <<= 1) {
        int u = (t >= off) ? sm[t - off] : 0;
        __syncthreads();
        sm[t] += u;
        __syncthreads();
    }
    d_bbase[t] = sm[t] - v;
}

__global__ __launch_bounds__(THREADS)
void scatter_kernel(const float2* __restrict__ x) {
    int i = blockIdx.x * blockDim.x + threadIdx.x;
    float2 p = x[i];
    unsigned b = bucket_of(p);
    int pos = d_bbase[b >> 10] + atomicAdd(&d_offs[b], 1);
    d_pts[pos] = make_float4(p.x, p.y, __int_as_float(i), 0.0f);
}

__global__ __launch_bounds__(THREADS)
void hashenc_kernel(const float2* __restrict__ tables,
                    float* __restrict__ out,
                    ResArr res)
{
    __shared__ float  s_out[THREADS * 33];   // stride-33 pad
    __shared__ float2 s_cache[CACHE_ENT];
    __shared__ int    s_x0[LEVELS], s_y0[LEVELS], s_W[LEVELS];
    __shared__ int    s_base[LEVELS], s_cnt[LEVELS];
    __shared__ float  s_red[32];

    int tid  = threadIdx.x;
    int lane = tid & 31;
    int w    = tid >> 5;
    int j    = blockIdx.x * THREADS + tid;

    float4 pk = d_pts[j];
    float px = pk.x, py = pk.y;
    int   n  = __float_as_int(pk.z);

    // ---- block bounding box ----
    float mnx = px, mxx = px, mny = py, mxy = py;
#pragma unroll
    for (int o = 16; o; o >>= 1) {
        mnx = fminf(mnx, __shfl_xor_sync(0xFFFFFFFFu, mnx, o));
        mxx = fmaxf(mxx, __shfl_xor_sync(0xFFFFFFFFu, mxx, o));
        mny = fminf(mny, __shfl_xor_sync(0xFFFFFFFFu, mny, o));
        mxy = fmaxf(mxy, __shfl_xor_sync(0xFFFFFFFFu, mxy, o));
    }
    if (lane == 0) {
        s_red[w] = mnx; s_red[8 + w] = mxx;
        s_red[16 + w] = mny; s_red[24 + w] = mxy;
    }
    __syncthreads();
    if (tid == 0) {
        float a = s_red[0], b = s_red[8], c = s_red[16], d = s_red[24];
        for (int i = 1; i < 8; ++i) {
            a = fminf(a, s_red[i]);      b = fmaxf(b, s_red[8 + i]);
            c = fminf(c, s_red[16 + i]); d = fmaxf(d, s_red[24 + i]);
        }
        int cap = 0;
        for (int l = 0; l < LEVELS; ++l) {
            float r = res.r[l];
            int x0 = (int)floorf(a * r), x1 = (int)floorf(b * r);
            int y0 = (int)floorf(c * r), y1 = (int)floorf(d * r);
            int W = x1 - x0 + 2, H = y1 - y0 + 2;   // +1 cell range, +1 corner
            int cnt = W * H;
            if (cap + cnt <= CACHE_ENT) { s_base[l] = cap; cap += cnt; }
            else                        { s_base[l] = -1; }
            s_x0[l] = x0; s_y0[l] = y0; s_W[l] = W; s_cnt[l] = cnt;
        }
    }
    __syncthreads();

    // ---- cooperative hash-fill of the table cache ----
    for (int l = 0; l < LEVELS; ++l) {
        int base = s_base[l];
        if (base < 0) continue;
        int W = s_W[l], cnt = s_cnt[l], x0 = s_x0[l], y0 = s_y0[l];
        const float2* t = tables + (size_t)l * TABLE_SIZE;
        for (int i = tid; i < cnt; i += THREADS) {
            int cx = x0 + i % W;
            int cy = y0 + i / W;
            unsigned h = ((unsigned)cx ^ ((unsigned)cy * PRIME)) & HMASK;
            s_cache[base + i] = __ldg(t + h);
        }
    }
    __syncthreads();

    // ---- per-point interpolation ----
#pragma unroll
    for (int l = 0; l < LEVELS; ++l) {
        float r  = res.r[l];
        float sx = px * r;
        float sy = py * r;
        float gxf = floorf(sx);
        float gyf = floorf(sy);
        float fx = sx - gxf;
        float fy = sy - gyf;
        float ox = 1.0f - fx;
        float oy = 1.0f - fy;
        int gx = (int)gxf;
        int gy = (int)gyf;

        float2 f00, f10, f01, f11;
        int base = s_base[l];             // block-uniform
        if (base >= 0) {
            int W = s_W[l];
            int idx = base + (gy - s_y0[l]) * W + (gx - s_x0[l]);
            f00 = s_cache[idx];
            f10 = s_cache[idx + 1];
            f01 = s_cache[idx + W];
            f11 = s_cache[idx + W + 1];
        } else {                          // rare fallback (Morton jump)
            unsigned hy0 = (unsigned)gy * PRIME;
            unsigned hy1 = hy0 + PRIME;
            unsigned ux  = (unsigned)gx;
            const float2* t = tables + (size_t)l * TABLE_SIZE;
            f00 = __ldg(t + (( ux        ^ hy0) & HMASK));
            f10 = __ldg(t + (((ux + 1u)  ^ hy0) & HMASK));
            f01 = __ldg(t + (( ux        ^ hy1) & HMASK));
            f11 = __ldg(t + (((ux + 1u)  ^ hy1) & HMASK));
        }

        float w00 = fx * fy;
        float w10 = ox * fy;
        float w01 = fx * oy;
        float w11 = ox * oy;

        s_out[tid * 33 + l] =
            (w00 * f00.x + w10 * f10.x) + (w01 * f01.x + w11 * f11.x);
        s_out[tid * 33 + 16 + l] =
            (w00 * f00.y + w10 * f10.y) + (w01 * f01.y + w11 * f11.y);
    }
    __syncthreads();

    // ---- warp-cooperative coalesced row writes ----
    int rbase = blockIdx.x * THREADS;
    for (int rrow = w; rrow < THREADS; rrow += THREADS / 32) {
        int nn = __float_as_int(d_pts[rbase + rrow].z);   // broadcast
        out[(size_t)nn * 32 + lane] = s_out[rrow * 33 + lane];
    }
}

extern "C" void kernel_launch(void* const* d_in, const int* in_sizes, int n_in,
                              void* d_out, int out_size)
{
    // Exact float64 replication of the reference _RESOLUTIONS computation.
    ResArr res;
    double b = exp((log(512.0) - log(16.0)) / 15.0);
    for (int l = 0; l < LEVELS; ++l) {
        double pw;
        if (l == 0)      pw = 1.0;
        else if (l == 1) pw = b;
        else             pw = pow(b, (double)l);
        res.r[l] = (float)floor(16.0 * pw);
    }

    const float2* x      = (const float2*)d_in[0];
    const float2* tables = (const float2*)d_in[1];
    float*        out    = (float*)d_out;

    zero_hist_kernel<<<NBUCKETS / THREADS, THREADS>>>();
    hist_kernel<<<NPTS / THREADS, THREADS>>>(x);
    scan1_kernel<<<NSCANBLK, SCAN_BLK>>>();
    scan2_kernel<<<1, NSCANBLK>>>();
    scatter_kernel<<<NPTS / THREADS, THREADS>>>(x);
    hashenc_kernel<<<NPTS / THREADS, THREADS>>>(tables, out, res);
}

// round 6
// speedup vs baseline: 1.5006x; 1.5006x over previous
#include <cuda_runtime.h>
#include <math.h>

#define LEVELS 16
#define TABLE_SIZE 524288
#define HMASK (TABLE_SIZE - 1)
#define NPTS 1048576
#define PRIME 2654435761u
#define THREADS 256
#define NBUCKETS 65536           // 256 x 256 Morton buckets, ~16 pts each
#define SCAN_BLK 1024
#define NSCANBLK (NBUCKETS / SCAN_BLK)   // 64

struct ResArr { float r[LEVELS]; };

// Scratch (__device__ globals: the sanctioned no-allocation path)
__device__ int    d_hist[NBUCKETS];
__device__ int    d_offs[NBUCKETS];
__device__ int    d_bsum[NSCANBLK];
__device__ int    d_bbase[NSCANBLK];
__device__ int    d_done;
__device__ float4 d_pts[NPTS];   // (x, y, bitcast(orig index), pad)

__device__ __forceinline__ unsigned expand8(unsigned v) {
    v = (v | (v << 4)) & 0x0F0Fu;
    v = (v | (v << 2)) & 0x3333u;
    v = (v | (v << 1)) & 0x5555u;
    return v;
}
__device__ __forceinline__ unsigned bucket_of(float2 p) {
    unsigned bx = (unsigned)(int)(p.x * 256.0f);
    unsigned by = (unsigned)(int)(p.y * 256.0f);
    bx = bx > 255u ? 255u : bx;
    by = by > 255u ? 255u : by;
    return expand8(bx) | (expand8(by) << 1);
}

__global__ void zero_hist_kernel() {
    int i = blockIdx.x * blockDim.x + threadIdx.x;
    d_hist[i] = 0;
    if (i == 0) d_done = 0;
}

__global__ __launch_bounds__(THREADS)
void hist_kernel(const float2* __restrict__ x) {
    int i = blockIdx.x * blockDim.x + threadIdx.x;
    atomicAdd(&d_hist[bucket_of(x[i])], 1);
}

// Per-chunk exclusive scan; the LAST block also scans the 64 chunk sums.
__global__ __launch_bounds__(SCAN_BLK)
void scan_kernel() {
    __shared__ int sm[SCAN_BLK];
    __shared__ bool is_last;
    int t = threadIdx.x;
    int i = blockIdx.x * SCAN_BLK + t;
    int v = d_hist[i];
    sm[t] = v;
    __syncthreads();
    for (int off = 1; off < SCAN_BLK; off <<= 1) {
        int u = (t >= off) ? sm[t - off] : 0;
        __syncthreads();
        sm[t] += u;
        __syncthreads();
    }
    int incl = sm[t];
    d_offs[i] = incl - v;                 // within-chunk exclusive prefix
    if (t == SCAN_BLK - 1) d_bsum[blockIdx.x] = incl;

    __threadfence();
    if (t == 0) is_last = (atomicAdd(&d_done, 1) == NSCANBLK - 1);
    __syncthreads();
    if (is_last) {                        // block-uniform branch
        int bv = (t < NSCANBLK) ? d_bsum[t] : 0;
        sm[t] = bv;
        __syncthreads();
        if (t < NSCANBLK) {
            int run = 0;
            for (int k = 0; k < t; ++k) run += sm[k];   // 64x64 smem: trivial
            d_bbase[t] = run;
        }
    }
}

__global__ __launch_bounds__(THREADS)
void scatter_kernel(const float2* __restrict__ x) {
    int i = blockIdx.x * blockDim.x + threadIdx.x;
    float2 p = x[i];
    unsigned b = bucket_of(p);
    int pos = d_bbase[b >> 10] + atomicAdd(&d_offs[b], 1);
    d_pts[pos] = make_float4(p.x, p.y, __int_as_float(i), 0.0f);
}

__global__ __launch_bounds__(THREADS)
void hashenc_kernel(const float2* __restrict__ tables,
                    float* __restrict__ out,
                    ResArr res)
{
    __shared__ float s_out[THREADS * 33];   // stride-33 pad: conflict-free
    int tid  = threadIdx.x;
    int lane = tid & 31;
    int w    = tid >> 5;
    int j    = blockIdx.x * THREADS + tid;

    float4 pk = d_pts[j];
    float px = pk.x, py = pk.y;

#pragma unroll
    for (int l = 0; l < LEVELS; ++l) {
        const float2* t = tables + (size_t)l * TABLE_SIZE;
        float r  = res.r[l];
        float sx = px * r;
        float sy = py * r;
        float gxf = floorf(sx);
        float gyf = floorf(sy);
        float fx = sx - gxf;
        float fy = sy - gyf;
        float ox = 1.0f - fx;
        float oy = 1.0f - fy;

        unsigned gx = (unsigned)(int)gxf;
        unsigned gy = (unsigned)(int)gyf;
        unsigned hy0 = gy * PRIME;
        unsigned hy1 = hy0 + PRIME;

        float2 f00 = __ldg(t + (( gx        ^ hy0) & HMASK));
        float2 f10 = __ldg(t + (((gx + 1u)  ^ hy0) & HMASK));
        float2 f01 = __ldg(t + (( gx        ^ hy1) & HMASK));
        float2 f11 = __ldg(t + (((gx + 1u)  ^ hy1) & HMASK));

        float w00 = fx * fy;
        float w10 = ox * fy;
        float w01 = fx * oy;
        float w11 = ox * oy;

        s_out[tid * 33 + l] =
            (w00 * f00.x + w10 * f10.x) + (w01 * f01.x + w11 * f11.x);
        s_out[tid * 33 + 16 + l] =
            (w00 * f00.y + w10 * f10.y) + (w01 * f01.y + w11 * f11.y);
    }
    __syncthreads();

    // Warp-cooperative coalesced row writes (one 128B row per iteration).
    int rbase = blockIdx.x * THREADS;
    for (int rrow = w; rrow < THREADS; rrow += THREADS / 32) {
        int nn = __float_as_int(d_pts[rbase + rrow].z);   // broadcast load
        out[(size_t)nn * 32 + lane] = s_out[rrow * 33 + lane];
    }
}

extern "C" void kernel_launch(void* const* d_in, const int* in_sizes, int n_in,
                              void* d_out, int out_size)
{
    // Exact float64 replication of the reference _RESOLUTIONS computation.
    ResArr res;
    double b = exp((log(512.0) - log(16.0)) / 15.0);
    for (int l = 0; l < LEVELS; ++l) {
        double pw;
        if (l == 0)      pw = 1.0;
        else if (l == 1) pw = b;
        else             pw = pow(b, (double)l);
        res.r[l] = (float)floor(16.0 * pw);
    }

    const float2* x      = (const float2*)d_in[0];
    const float2* tables = (const float2*)d_in[1];
    float*        out    = (float*)d_out;

    zero_hist_kernel<<<NBUCKETS / THREADS, THREADS>>>();
    hist_kernel<<<NPTS / THREADS, THREADS>>>(x);
    scan_kernel<<<NSCANBLK, SCAN_BLK>>>();
    scatter_kernel<<<NPTS / THREADS, THREADS>>>(x);
    hashenc_kernel<<<NPTS / THREADS, THREADS>>>(tables, out, res);
}

// round 7
// speedup vs baseline: 1.5344x; 1.0225x over previous
#include <cuda_runtime.h>
#include <math.h>

#define LEVELS 16
#define TABLE_SIZE 524288
#define HMASK (TABLE_SIZE - 1)
#define NPTS 1048576
#define PRIME 2654435761u
#define THREADS 256
#define GRID_B 512                        // 512 x 512 Morton buckets, ~4 pts each
#define NBUCKETS (GRID_B * GRID_B)        // 262144
#define SCAN_BLK 1024
#define NSCANBLK (NBUCKETS / SCAN_BLK)    // 256

struct ResArr { float r[LEVELS]; };

// Scratch (__device__ globals: the sanctioned no-allocation path)
__device__ int    d_hist[NBUCKETS];
__device__ int    d_offs[NBUCKETS];
__device__ int    d_bsum[NSCANBLK];
__device__ int    d_bbase[NSCANBLK];
__device__ int    d_done;
__device__ float4 d_pts[NPTS];   // (x, y, bitcast(orig index), pad)

__device__ __forceinline__ unsigned expand16(unsigned v) {
    v = (v | (v << 8)) & 0x00FF00FFu;
    v = (v | (v << 4)) & 0x0F0F0F0Fu;
    v = (v | (v << 2)) & 0x33333333u;
    v = (v | (v << 1)) & 0x55555555u;
    return v;
}
__device__ __forceinline__ unsigned bucket_of(float2 p) {
    unsigned bx = (unsigned)(int)(p.x * (float)GRID_B);
    unsigned by = (unsigned)(int)(p.y * (float)GRID_B);
    bx = bx > (GRID_B - 1u) ? (GRID_B - 1u) : bx;
    by = by > (GRID_B - 1u) ? (GRID_B - 1u) : by;
    return expand16(bx) | (expand16(by) << 1);
}

__global__ void zero_hist_kernel() {
    int i = blockIdx.x * blockDim.x + threadIdx.x;
    d_hist[i] = 0;
    if (i == 0) d_done = 0;
}

__global__ __launch_bounds__(THREADS)
void hist_kernel(const float2* __restrict__ x) {
    int i = blockIdx.x * blockDim.x + threadIdx.x;
    atomicAdd(&d_hist[bucket_of(x[i])], 1);
}

// Per-chunk exclusive scan; the LAST block also scans the 256 chunk sums.
__global__ __launch_bounds__(SCAN_BLK)
void scan_kernel() {
    __shared__ int sm[SCAN_BLK];
    __shared__ bool is_last;
    int t = threadIdx.x;
    int i = blockIdx.x * SCAN_BLK + t;
    int v = d_hist[i];
    sm[t] = v;
    __syncthreads();
    for (int off = 1; off < SCAN_BLK; off <<= 1) {
        int u = (t >= off) ? sm[t - off] : 0;
        __syncthreads();
        sm[t] += u;
        __syncthreads();
    }
    int incl = sm[t];
    d_offs[i] = incl - v;                 // within-chunk exclusive prefix
    if (t == SCAN_BLK - 1) d_bsum[blockIdx.x] = incl;

    __threadfence();
    if (t == 0) is_last = (atomicAdd(&d_done, 1) == NSCANBLK - 1);
    __syncthreads();
    if (is_last) {                        // block-uniform branch
        int bv = (t < NSCANBLK) ? d_bsum[t] : 0;
        sm[t] = bv;
        __syncthreads();
        // Hillis-Steele over the first NSCANBLK slots (all 1024 threads step
        // together; slots >= NSCANBLK are scanned too but unused)
        for (int off = 1; off < NSCANBLK; off <<= 1) {
            int u = (t >= off) ? sm[t - off] : 0;
            __syncthreads();
            sm[t] += u;
            __syncthreads();
        }
        if (t < NSCANBLK) d_bbase[t] = sm[t] - bv;
    }
}

__global__ __launch_bounds__(THREADS)
void scatter_kernel(const float2* __restrict__ x) {
    int i = blockIdx.x * blockDim.x + threadIdx.x;
    float2 p = x[i];
    unsigned b = bucket_of(p);
    int pos = d_bbase[b >> 10] + atomicAdd(&d_offs[b], 1);
    d_pts[pos] = make_float4(p.x, p.y, __int_as_float(i), 0.0f);
}

__global__ __launch_bounds__(THREADS)
void hashenc_kernel(const float2* __restrict__ tables,
                    float* __restrict__ out,
                    ResArr res)
{
    __shared__ float s_out[THREADS * 33];   // stride-33 pad: conflict-free
    int tid  = threadIdx.x;
    int lane = tid & 31;
    int w    = tid >> 5;
    int j    = blockIdx.x * THREADS + tid;

    float4 pk = d_pts[j];
    float px = pk.x, py = pk.y;

#pragma unroll
    for (int l = 0; l < LEVELS; ++l) {
        const float2* t = tables + (size_t)l * TABLE_SIZE;
        float r  = res.r[l];
        float sx = px * r;
        float sy = py * r;
        float gxf = floorf(sx);
        float gyf = floorf(sy);
        float fx = sx - gxf;
        float fy = sy - gyf;
        float ox = 1.0f - fx;
        float oy = 1.0f - fy;

        unsigned gx = (unsigned)(int)gxf;
        unsigned gy = (unsigned)(int)gyf;
        unsigned hy0 = gy * PRIME;
        unsigned hy1 = hy0 + PRIME;

        float2 f00 = __ldg(t + (( gx        ^ hy0) & HMASK));
        float2 f10 = __ldg(t + (((gx + 1u)  ^ hy0) & HMASK));
        float2 f01 = __ldg(t + (( gx        ^ hy1) & HMASK));
        float2 f11 = __ldg(t + (((gx + 1u)  ^ hy1) & HMASK));

        float w00 = fx * fy;
        float w10 = ox * fy;
        float w01 = fx * oy;
        float w11 = ox * oy;

        s_out[tid * 33 + l] =
            (w00 * f00.x + w10 * f10.x) + (w01 * f01.x + w11 * f11.x);
        s_out[tid * 33 + 16 + l] =
            (w00 * f00.y + w10 * f10.y) + (w01 * f01.y + w11 * f11.y);
    }
    __syncthreads();

    // Warp-cooperative coalesced row writes (one 128B row per iteration).
    int rbase = blockIdx.x * THREADS;
    for (int rrow = w; rrow < THREADS; rrow += THREADS / 32) {
        int nn = __float_as_int(d_pts[rbase + rrow].z);   // broadcast load
        out[(size_t)nn * 32 + lane] = s_out[rrow * 33 + lane];
    }
}

extern "C" void kernel_launch(void* const* d_in, const int* in_sizes, int n_in,
                              void* d_out, int out_size)
{
    // Exact float64 replication of the reference _RESOLUTIONS computation.
    ResArr res;
    double b = exp((log(512.0) - log(16.0)) / 15.0);
    for (int l = 0; l < LEVELS; ++l) {
        double pw;
        if (l == 0)      pw = 1.0;
        else if (l == 1) pw = b;
        else             pw = pow(b, (double)l);
        res.r[l] = (float)floor(16.0 * pw);
    }

    const float2* x      = (const float2*)d_in[0];
    const float2* tables = (const float2*)d_in[1];
    float*        out    = (float*)d_out;

    zero_hist_kernel<<<NBUCKETS / THREADS, THREADS>>>();
    hist_kernel<<<NPTS / THREADS, THREADS>>>(x);
    scan_kernel<<<NSCANBLK, SCAN_BLK>>>();
    scatter_kernel<<<NPTS / THREADS, THREADS>>>(x);
    hashenc_kernel<<<NPTS / THREADS, THREADS>>>(tables, out, res);
}

// round 8
// speedup vs baseline: 1.6058x; 1.0465x over previous
#include <cuda_runtime.h>
#include <math.h>

#define LEVELS 16
#define TABLE_SIZE 524288
#define HMASK (TABLE_SIZE - 1)
#define NPTS 1048576
#define PRIME 2654435761u
#define THREADS 256
#define GRID_B 512                        // 512 x 512 Morton buckets
#define NBUCKETS (GRID_B * GRID_B)        // 262144
#define SCAN_BLK 1024
#define NSCANBLK (NBUCKETS / SCAN_BLK)    // 256
#define SC_PER 4                          // points per scatter thread (MLP)
#define SSTR 17                           // staging stride (16 + 1 pad)

struct ResArr { float r[LEVELS]; };

// Scratch (__device__ globals: the sanctioned no-allocation path)
__device__ int    d_hist[NBUCKETS];       // zero-initialized at module load;
__device__ int    d_done;                 // re-zeroed by hashenc tail each call
__device__ int    d_offs[NBUCKETS];
__device__ int    d_bsum[NSCANBLK];
__device__ int    d_bbase[NSCANBLK];
__device__ float4 d_pts[NPTS];            // (x, y, bitcast(orig index), pad)

__device__ __forceinline__ unsigned expand16(unsigned v) {
    v = (v | (v << 8)) & 0x00FF00FFu;
    v = (v | (v << 4)) & 0x0F0F0F0Fu;
    v = (v | (v << 2)) & 0x33333333u;
    v = (v | (v << 1)) & 0x55555555u;
    return v;
}
__device__ __forceinline__ unsigned bucket_of(float2 p) {
    unsigned bx = (unsigned)(int)(p.x * (float)GRID_B);
    unsigned by = (unsigned)(int)(p.y * (float)GRID_B);
    bx = bx > (GRID_B - 1u) ? (GRID_B - 1u) : bx;
    by = by > (GRID_B - 1u) ? (GRID_B - 1u) : by;
    return expand16(bx) | (expand16(by) << 1);
}

__global__ __launch_bounds__(THREADS)
void hist_kernel(const float2* __restrict__ x) {
    int i = blockIdx.x * blockDim.x + threadIdx.x;
    atomicAdd(&d_hist[bucket_of(x[i])], 1);
}

// Per-chunk exclusive scan; the LAST block also scans the 256 chunk sums.
__global__ __launch_bounds__(SCAN_BLK)
void scan_kernel() {
    __shared__ int sm[SCAN_BLK];
    __shared__ bool is_last;
    int t = threadIdx.x;
    int i = blockIdx.x * SCAN_BLK + t;
    int v = d_hist[i];
    sm[t] = v;
    __syncthreads();
    for (int off = 1; off < SCAN_BLK; off <<= 1) {
        int u = (t >= off) ? sm[t - off] : 0;
        __syncthreads();
        sm[t] += u;
        __syncthreads();
    }
    int incl = sm[t];
    d_offs[i] = incl - v;                 // within-chunk exclusive prefix
    if (t == SCAN_BLK - 1) d_bsum[blockIdx.x] = incl;

    __threadfence();
    if (t == 0) is_last = (atomicAdd(&d_done, 1) == NSCANBLK - 1);
    __syncthreads();
    if (is_last) {                        // block-uniform branch
        int bv = (t < NSCANBLK) ? d_bsum[t] : 0;
        sm[t] = bv;
        __syncthreads();
        for (int off = 1; off < NSCANBLK; off <<= 1) {
            int u = (t >= off) ? sm[t - off] : 0;
            __syncthreads();
            sm[t] += u;
            __syncthreads();
        }
        if (t < NSCANBLK) d_bbase[t] = sm[t] - bv;
    }
}

// 4 points per thread: batch the independent atomics, then the stores (MLP=4).
__global__ __launch_bounds__(THREADS)
void scatter_kernel(const float2* __restrict__ x) {
    const int Q = NPTS / SC_PER;
    int t = blockIdx.x * blockDim.x + threadIdx.x;
    float2   p[SC_PER];
    unsigned b[SC_PER];
    int      pos[SC_PER];
#pragma unroll
    for (int k = 0; k < SC_PER; ++k) {
        p[k] = x[t + k * Q];
        b[k] = bucket_of(p[k]);
    }
#pragma unroll
    for (int k = 0; k < SC_PER; ++k)
        pos[k] = d_bbase[b[k] >> 10] + atomicAdd(&d_offs[b[k]], 1);
#pragma unroll
    for (int k = 0; k < SC_PER; ++k)
        d_pts[pos[k]] = make_float4(p[k].x, p[k].y,
                                    __int_as_float(t + k * Q), 0.0f);
}

__global__ __launch_bounds__(THREADS, 8)
void hashenc_kernel(const float2* __restrict__ tables,
                    float* __restrict__ out,
                    ResArr res)
{
    __shared__ float s_out[THREADS * SSTR];   // 17.4 KB -> 8 CTAs/SM
    int tid  = threadIdx.x;
    int lane = tid & 31;
    int w    = tid >> 5;
    int j    = blockIdx.x * THREADS + tid;
    int rbase = blockIdx.x * THREADS;

    float4 pk = d_pts[j];
    float px = pk.x, py = pk.y;

#pragma unroll
    for (int ph = 0; ph < 2; ++ph) {
        if (ph) __syncthreads();              // write-loop done before restage
#pragma unroll
        for (int li = 0; li < 8; ++li) {
            const int l = ph * 8 + li;
            const float2* t = tables + (size_t)l * TABLE_SIZE;
            float r  = res.r[l];
            float sx = px * r;
            float sy = py * r;
            float gxf = floorf(sx);
            float gyf = floorf(sy);
            float fx = sx - gxf;
            float fy = sy - gyf;
            float ox = 1.0f - fx;
            float oy = 1.0f - fy;

            unsigned gx = (unsigned)(int)gxf;
            unsigned gy = (unsigned)(int)gyf;
            unsigned hy0 = gy * PRIME;
            unsigned hy1 = hy0 + PRIME;

            float2 f00 = __ldg(t + (( gx        ^ hy0) & HMASK));
            float2 f10 = __ldg(t + (((gx + 1u)  ^ hy0) & HMASK));
            float2 f01 = __ldg(t + (( gx        ^ hy1) & HMASK));
            float2 f11 = __ldg(t + (((gx + 1u)  ^ hy1) & HMASK));

            float w00 = fx * fy;
            float w10 = ox * fy;
            float w01 = fx * oy;
            float w11 = ox * oy;

            s_out[tid * SSTR + li] =
                (w00 * f00.x + w10 * f10.x) + (w01 * f01.x + w11 * f11.x);
            s_out[tid * SSTR + 8 + li] =
                (w00 * f00.y + w10 * f10.y) + (w01 * f01.y + w11 * f11.y);
        }
        __syncthreads();

        // Write this phase's 16 floats/point: warp covers 2 rows x 16 cols.
        // cols: c<8 -> feature0 (ph*8+c), c>=8 -> feature1 (16 + ph*8 + c-8).
        int c   = lane & 15;
        int col = (c < 8) ? (ph * 8 + c) : (16 + ph * 8 + (c - 8));
        for (int k = w; k < THREADS / 2; k += THREADS / 32) {
            int rrow = 2 * k + (lane >> 4);
            int nn = __float_as_int(d_pts[rbase + rrow].z);  // 2 addrs/warp
            out[(size_t)nn * 32 + col] = s_out[rrow * SSTR + c];
        }
    }

    // Tail: zero the histogram (and d_done) for the next call. Globals are
    // zero-initialized at module load, so the first call is also correct.
    int g = blockIdx.x * THREADS + tid;
    if (g < NBUCKETS) d_hist[g] = 0;
    if (g == 0) d_done = 0;
}

extern "C" void kernel_launch(void* const* d_in, const int* in_sizes, int n_in,
                              void* d_out, int out_size)
{
    // Exact float64 replication of the reference _RESOLUTIONS computation.
    ResArr res;
    double b = exp((log(512.0) - log(16.0)) / 15.0);
    for (int l = 0; l < LEVELS; ++l) {
        double pw;
        if (l == 0)      pw = 1.0;
        else if (l == 1) pw = b;
        else             pw = pow(b, (double)l);
        res.r[l] = (float)floor(16.0 * pw);
    }

    const float2* x      = (const float2*)d_in[0];
    const float2* tables = (const float2*)d_in[1];
    float*        out    = (float*)d_out;

    hist_kernel<<<NPTS / THREADS, THREADS>>>(x);
    scan_kernel<<<NSCANBLK, SCAN_BLK>>>();
    scatter_kernel<<<NPTS / SC_PER / THREADS, THREADS>>>(x);
    hashenc_kernel<<<NPTS / THREADS, THREADS>>>(tables, out, res);
}

// round 9
// speedup vs baseline: 1.7967x; 1.1189x over previous
#include <cuda_runtime.h>
#include <math.h>

#define LEVELS 16
#define TABLE_SIZE 524288
#define HMASK (TABLE_SIZE - 1)
#define NPTS 1048576
#define PRIME 2654435761u
#define THREADS 256
#define GRID_B 512                        // 512 x 512 Morton buckets
#define NBUCKETS (GRID_B * GRID_B)        // 262144
#define SCAN_BLK 1024
#define NSCANBLK (NBUCKETS / SCAN_BLK)    // 256
#define SC_PER 4                          // points per scatter thread (MLP)
#define HI_PER 4                          // points per hist thread (MLP)
#define SSTR2 9                           // staging stride in float2 (8 + pad)

struct ResArr { float r[LEVELS]; };

// Scratch (__device__ globals: the sanctioned no-allocation path)
__device__ int    d_hist[NBUCKETS];       // zero-initialized at module load;
__device__ int    d_done;                 // re-zeroed by hashenc tail each call
__device__ int    d_offs[NBUCKETS];
__device__ int    d_bsum[NSCANBLK];
__device__ int    d_bbase[NSCANBLK];
__device__ float4 d_pts[NPTS];            // (x, y, bitcast(orig index), pad)

__device__ __forceinline__ unsigned expand16(unsigned v) {
    v = (v | (v << 8)) & 0x00FF00FFu;
    v = (v | (v << 4)) & 0x0F0F0F0Fu;
    v = (v | (v << 2)) & 0x33333333u;
    v = (v | (v << 1)) & 0x55555555u;
    return v;
}
__device__ __forceinline__ unsigned bucket_of(float px, float py) {
    unsigned bx = (unsigned)(int)(px * (float)GRID_B);
    unsigned by = (unsigned)(int)(py * (float)GRID_B);
    bx = bx > (GRID_B - 1u) ? (GRID_B - 1u) : bx;
    by = by > (GRID_B - 1u) ? (GRID_B - 1u) : by;
    return expand16(bx) | (expand16(by) << 1);
}

// 4 points per thread via two coalesced float4 loads; batched atomics.
__global__ __launch_bounds__(THREADS)
void hist_kernel(const float4* __restrict__ x4) {
    const int QH = NPTS / 4;              // float4 count / 2 halves
    int t = blockIdx.x * blockDim.x + threadIdx.x;
    float4 a = x4[t];
    float4 b = x4[t + QH];
    atomicAdd(&d_hist[bucket_of(a.x, a.y)], 1);
    atomicAdd(&d_hist[bucket_of(a.z, a.w)], 1);
    atomicAdd(&d_hist[bucket_of(b.x, b.y)], 1);
    atomicAdd(&d_hist[bucket_of(b.z, b.w)], 1);
}

// Per-chunk exclusive scan; the LAST block also scans the 256 chunk sums.
__global__ __launch_bounds__(SCAN_BLK)
void scan_kernel() {
    __shared__ int sm[SCAN_BLK];
    __shared__ bool is_last;
    int t = threadIdx.x;
    int i = blockIdx.x * SCAN_BLK + t;
    int v = d_hist[i];
    sm[t] = v;
    __syncthreads();
    for (int off = 1; off < SCAN_BLK; off <<= 1) {
        int u = (t >= off) ? sm[t - off] : 0;
        __syncthreads();
        sm[t] += u;
        __syncthreads();
    }
    int incl = sm[t];
    d_offs[i] = incl - v;                 // within-chunk exclusive prefix
    if (t == SCAN_BLK - 1) d_bsum[blockIdx.x] = incl;

    __threadfence();
    if (t == 0) is_last = (atomicAdd(&d_done, 1) == NSCANBLK - 1);
    __syncthreads();
    if (is_last) {                        // block-uniform branch
        int bv = (t < NSCANBLK) ? d_bsum[t] : 0;
        sm[t] = bv;
        __syncthreads();
        for (int off = 1; off < NSCANBLK; off <<= 1) {
            int u = (t >= off) ? sm[t - off] : 0;
            __syncthreads();
            sm[t] += u;
            __syncthreads();
        }
        if (t < NSCANBLK) d_bbase[t] = sm[t] - bv;
    }
}

// 4 points per thread: batch the independent atomics, then the stores (MLP=4).
__global__ __launch_bounds__(THREADS)
void scatter_kernel(const float2* __restrict__ x) {
    const int Q = NPTS / SC_PER;
    int t = blockIdx.x * blockDim.x + threadIdx.x;
    float2   p[SC_PER];
    unsigned b[SC_PER];
    int      pos[SC_PER];
#pragma unroll
    for (int k = 0; k < SC_PER; ++k) {
        p[k] = x[t + k * Q];
        b[k] = bucket_of(p[k].x, p[k].y);
    }
#pragma unroll
    for (int k = 0; k < SC_PER; ++k)
        pos[k] = d_bbase[b[k] >> 10] + atomicAdd(&d_offs[b[k]], 1);
#pragma unroll
    for (int k = 0; k < SC_PER; ++k)
        d_pts[pos[k]] = make_float4(p[k].x, p[k].y,
                                    __int_as_float(t + k * Q), 0.0f);
}

__global__ __launch_bounds__(THREADS, 8)
void hashenc_kernel(const float2* __restrict__ tables,
                    float* __restrict__ out,
                    ResArr res)
{
    // Staging per phase: slot c<4 -> feature0 level-pair, c>=4 -> feature1.
    __shared__ float2 s2[THREADS * SSTR2];    // 18.4 KB
    __shared__ int    s_idx[THREADS];         // 1 KB
    int tid  = threadIdx.x;
    int lane = tid & 31;
    int w    = tid >> 5;
    int j    = blockIdx.x * THREADS + tid;

    float4 pk = d_pts[j];
    float px = pk.x, py = pk.y;
    s_idx[tid] = __float_as_int(pk.z);

#pragma unroll
    for (int ph = 0; ph < 2; ++ph) {
        if (ph) __syncthreads();              // writes done before restage
        float a0e = 0.0f, a1e = 0.0f;
#pragma unroll
        for (int li = 0; li < 8; ++li) {
            const int l = ph * 8 + li;
            const float2* t = tables + (size_t)l * TABLE_SIZE;
            float r  = res.r[l];
            float sx = px * r;
            float sy = py * r;
            float gxf = floorf(sx);
            float gyf = floorf(sy);
            float fx = sx - gxf;
            float fy = sy - gyf;
            float ox = 1.0f - fx;
            float oy = 1.0f - fy;

            unsigned gx = (unsigned)(int)gxf;
            unsigned gy = (unsigned)(int)gyf;
            unsigned hy0 = gy * PRIME;
            unsigned hy1 = hy0 + PRIME;

            float2 f00 = __ldg(t + (( gx        ^ hy0) & HMASK));
            float2 f10 = __ldg(t + (((gx + 1u)  ^ hy0) & HMASK));
            float2 f01 = __ldg(t + (( gx        ^ hy1) & HMASK));
            float2 f11 = __ldg(t + (((gx + 1u)  ^ hy1) & HMASK));

            float w00 = fx * fy;
            float w10 = ox * fy;
            float w01 = fx * oy;
            float w11 = ox * oy;

            float a0 = (w00 * f00.x + w10 * f10.x) + (w01 * f01.x + w11 * f11.x);
            float a1 = (w00 * f00.y + w10 * f10.y) + (w01 * f01.y + w11 * f11.y);

            if (li & 1) {                     // STS.64 per level-pair
                s2[tid * SSTR2 + (li >> 1)]     = make_float2(a0e, a0);
                s2[tid * SSTR2 + 4 + (li >> 1)] = make_float2(a1e, a1);
            } else { a0e = a0; a1e = a1; }
        }
        __syncthreads();

        // Write loop: lane handles one float2 (two adjacent out columns);
        // warp covers 4 rows x 8 slots per iteration -> 8 iterations/phase.
        int c    = lane & 7;
        int rsub = lane >> 3;
        int col  = (c < 4) ? (ph * 8 + 2 * c) : (8 + ph * 8 + 2 * c);
        for (int k = w; k < THREADS / 4; k += THREADS / 32) {
            int rrow = 4 * k + rsub;
            int nn = s_idx[rrow];             // broadcast LDS
            float2 v = s2[rrow * SSTR2 + c];
            *reinterpret_cast<float2*>(&out[(size_t)nn * 32 + col]) = v;
        }
    }

    // Tail: zero the histogram (and d_done) for the next call. Globals are
    // zero-initialized at module load, so the first call is also correct.
    int g = blockIdx.x * THREADS + tid;
    if (g < NBUCKETS) d_hist[g] = 0;
    if (g == 0) d_done = 0;
}

extern "C" void kernel_launch(void* const* d_in, const int* in_sizes, int n_in,
                              void* d_out, int out_size)
{
    // Exact float64 replication of the reference _RESOLUTIONS computation.
    ResArr res;
    double b = exp((log(512.0) - log(16.0)) / 15.0);
    for (int l = 0; l < LEVELS; ++l) {
        double pw;
        if (l == 0)      pw = 1.0;
        else if (l == 1) pw = b;
        else             pw = pow(b, (double)l);
        res.r[l] = (float)floor(16.0 * pw);
    }

    const float2* x      = (const float2*)d_in[0];
    const float2* tables = (const float2*)d_in[1];
    float*        out    = (float*)d_out;

    hist_kernel<<<NPTS / HI_PER / THREADS, THREADS>>>((const float4*)x);
    scan_kernel<<<NSCANBLK, SCAN_BLK>>>();
    scatter_kernel<<<NPTS / SC_PER / THREADS, THREADS>>>(x);
    hashenc_kernel<<<NPTS / THREADS, THREADS>>>(tables, out, res);
}

// round 10
// speedup vs baseline: 1.8068x; 1.0056x over previous
#include <cuda_runtime.h>
#include <math.h>

#define LEVELS 16
#define TABLE_SIZE 524288
#define HMASK (TABLE_SIZE - 1)
#define NPTS 1048576
#define PRIME 2654435761u
#define THREADS 256
#define GRID_B 512                        // 512 x 512 Morton buckets
#define NBUCKETS (GRID_B * GRID_B)        // 262144
#define SCAN_BLK 1024
#define NSCANBLK (NBUCKETS / SCAN_BLK)    // 256
#define SC_PER 4                          // points per scatter thread (MLP)
#define HI_PER 4                          // points per hist thread (MLP)
#define SSTR2 9                           // staging stride in float2 (8 + pad)

struct ResArr { float r[LEVELS]; };

typedef unsigned long long u64;

// Scratch (__device__ globals: the sanctioned no-allocation path)
__device__ int    d_hist[NBUCKETS];       // zero-initialized at module load;
__device__ int    d_done;                 // re-zeroed by hashenc tail each call
__device__ int    d_offs[NBUCKETS];
__device__ int    d_bsum[NSCANBLK];
__device__ int    d_bbase[NSCANBLK];
__device__ float4 d_pts[NPTS];            // (x, y, bitcast(orig index), pad)

// ---- packed f32x2 helpers (sm_100+) ----
__device__ __forceinline__ u64 bcast2(float a) {
    u64 r; asm("mov.b64 %0, {%1, %1};" : "=l"(r) : "f"(a)); return r;
}
__device__ __forceinline__ u64 sub2(u64 a, u64 b) {
    u64 r; asm("sub.rn.f32x2 %0, %1, %2;" : "=l"(r) : "l"(a), "l"(b)); return r;
}
__device__ __forceinline__ u64 fma2(u64 a, u64 b, u64 c) {
    u64 r; asm("fma.rn.f32x2 %0, %1, %2, %3;" : "=l"(r) : "l"(a), "l"(b), "l"(c)); return r;
}
__device__ __forceinline__ void unpack2(u64 v, float& lo, float& hi) {
    asm("mov.b64 {%0, %1}, %2;" : "=f"(lo), "=f"(hi) : "l"(v));
}

__device__ __forceinline__ unsigned expand16(unsigned v) {
    v = (v | (v << 8)) & 0x00FF00FFu;
    v = (v | (v << 4)) & 0x0F0F0F0Fu;
    v = (v | (v << 2)) & 0x33333333u;
    v = (v | (v << 1)) & 0x55555555u;
    return v;
}
__device__ __forceinline__ unsigned bucket_of(float px, float py) {
    unsigned bx = (unsigned)(int)(px * (float)GRID_B);
    unsigned by = (unsigned)(int)(py * (float)GRID_B);
    bx = bx > (GRID_B - 1u) ? (GRID_B - 1u) : bx;
    by = by > (GRID_B - 1u) ? (GRID_B - 1u) : by;
    return expand16(bx) | (expand16(by) << 1);
}

// 4 points per thread via two coalesced float4 loads; batched atomics.
__global__ __launch_bounds__(THREADS)
void hist_kernel(const float4* __restrict__ x4) {
    const int QH = NPTS / 4;
    int t = blockIdx.x * blockDim.x + threadIdx.x;
    float4 a = x4[t];
    float4 b = x4[t + QH];
    atomicAdd(&d_hist[bucket_of(a.x, a.y)], 1);
    atomicAdd(&d_hist[bucket_of(a.z, a.w)], 1);
    atomicAdd(&d_hist[bucket_of(b.x, b.y)], 1);
    atomicAdd(&d_hist[bucket_of(b.z, b.w)], 1);
}

// Per-chunk exclusive scan; the LAST block also scans the 256 chunk sums.
__global__ __launch_bounds__(SCAN_BLK)
void scan_kernel() {
    __shared__ int sm[SCAN_BLK];
    __shared__ bool is_last;
    int t = threadIdx.x;
    int i = blockIdx.x * SCAN_BLK + t;
    int v = d_hist[i];
    sm[t] = v;
    __syncthreads();
    for (int off = 1; off < SCAN_BLK; off <<= 1) {
        int u = (t >= off) ? sm[t - off] : 0;
        __syncthreads();
        sm[t] += u;
        __syncthreads();
    }
    int incl = sm[t];
    d_offs[i] = incl - v;                 // within-chunk exclusive prefix
    if (t == SCAN_BLK - 1) d_bsum[blockIdx.x] = incl;

    __threadfence();
    if (t == 0) is_last = (atomicAdd(&d_done, 1) == NSCANBLK - 1);
    __syncthreads();
    if (is_last) {                        // block-uniform branch
        int bv = (t < NSCANBLK) ? d_bsum[t] : 0;
        sm[t] = bv;
        __syncthreads();
        for (int off = 1; off < NSCANBLK; off <<= 1) {
            int u = (t >= off) ? sm[t - off] : 0;
            __syncthreads();
            sm[t] += u;
            __syncthreads();
        }
        if (t < NSCANBLK) d_bbase[t] = sm[t] - bv;
    }
}

// 4 points per thread: batch the independent atomics, then the stores (MLP=4).
__global__ __launch_bounds__(THREADS)
void scatter_kernel(const float2* __restrict__ x) {
    const int Q = NPTS / SC_PER;
    int t = blockIdx.x * blockDim.x + threadIdx.x;
    float2   p[SC_PER];
    unsigned b[SC_PER];
    int      pos[SC_PER];
#pragma unroll
    for (int k = 0; k < SC_PER; ++k) {
        p[k] = x[t + k * Q];
        b[k] = bucket_of(p[k].x, p[k].y);
    }
#pragma unroll
    for (int k = 0; k < SC_PER; ++k)
        pos[k] = d_bbase[b[k] >> 10] + atomicAdd(&d_offs[b[k]], 1);
#pragma unroll
    for (int k = 0; k < SC_PER; ++k)
        d_pts[pos[k]] = make_float4(p[k].x, p[k].y,
                                    __int_as_float(t + k * Q), 0.0f);
}

__global__ __launch_bounds__(THREADS, 8)
void hashenc_kernel(const float2* __restrict__ tables,
                    float* __restrict__ out,
                    ResArr res)
{
    __shared__ float2 s2[THREADS * SSTR2];    // 18.4 KB
    __shared__ int    s_idx[THREADS];         // 1 KB
    int tid  = threadIdx.x;
    int lane = tid & 31;
    int w    = tid >> 5;
    int j    = blockIdx.x * THREADS + tid;

    float4 pk = d_pts[j];
    float px = pk.x, py = pk.y;
    s_idx[tid] = __float_as_int(pk.z);

    const u64* tu = reinterpret_cast<const u64*>(tables);

#pragma unroll
    for (int ph = 0; ph < 2; ++ph) {
        if (ph) __syncthreads();              // writes done before restage
        float a0e = 0.0f, a1e = 0.0f;
#pragma unroll
        for (int li = 0; li < 8; ++li) {
            const int l = ph * 8 + li;
            const u64* t = tu + (size_t)l * TABLE_SIZE;
            float r  = res.r[l];
            float sx = px * r;
            float sy = py * r;
            float gxf = floorf(sx);
            float gyf = floorf(sy);
            float fx = sx - gxf;
            float fy = sy - gyf;

            unsigned gx = (unsigned)(int)gxf;
            unsigned gy = (unsigned)(int)gyf;
            unsigned hy0 = gy * PRIME;
            unsigned hy1 = hy0 + PRIME;

            u64 F00 = __ldg(t + (( gx        ^ hy0) & HMASK));
            u64 F10 = __ldg(t + (((gx + 1u)  ^ hy0) & HMASK));
            u64 F01 = __ldg(t + (( gx        ^ hy1) & HMASK));
            u64 F11 = __ldg(t + (((gx + 1u)  ^ hy1) & HMASK));

            // bilinear with "reversed" weights: w00 = fx*fy etc.
            //   A = fy*(fx*F00 + (1-fx)*F10) + (1-fy)*(fx*F01 + (1-fx)*F11)
            u64 FX = bcast2(fx);
            u64 FY = bcast2(fy);
            u64 I0 = fma2(FX, sub2(F00, F10), F10);
            u64 I1 = fma2(FX, sub2(F01, F11), F11);
            u64 A  = fma2(FY, sub2(I0, I1), I1);

            float a0, a1;
            unpack2(A, a0, a1);

            if (li & 1) {                     // STS.64 per level-pair
                s2[tid * SSTR2 + (li >> 1)]     = make_float2(a0e, a0);
                s2[tid * SSTR2 + 4 + (li >> 1)] = make_float2(a1e, a1);
            } else { a0e = a0; a1e = a1; }
        }
        __syncthreads();

        // Write loop: lane handles one float2 (two adjacent out columns);
        // warp covers 4 rows x 8 slots per iteration -> 8 iterations/phase.
        int c    = lane & 7;
        int rsub = lane >> 3;
        int col  = (c < 4) ? (ph * 8 + 2 * c) : (8 + ph * 8 + 2 * c);
        for (int k = w; k < THREADS / 4; k += THREADS / 32) {
            int rrow = 4 * k + rsub;
            int nn = s_idx[rrow];             // broadcast LDS
            float2 v = s2[rrow * SSTR2 + c];
            *reinterpret_cast<float2*>(&out[(size_t)nn * 32 + col]) = v;
        }
    }

    // Tail: zero the histogram (and d_done) for the next call. Globals are
    // zero-initialized at module load, so the first call is also correct.
    int g = blockIdx.x * THREADS + tid;
    if (g < NBUCKETS) d_hist[g] = 0;
    if (g == 0) d_done = 0;
}

extern "C" void kernel_launch(void* const* d_in, const int* in_sizes, int n_in,
                              void* d_out, int out_size)
{
    // Exact float64 replication of the reference _RESOLUTIONS computation.
    ResArr res;
    double b = exp((log(512.0) - log(16.0)) / 15.0);
    for (int l = 0; l < LEVELS; ++l) {
        double pw;
        if (l == 0)      pw = 1.0;
        else if (l == 1) pw = b;
        else             pw = pow(b, (double)l);
        res.r[l] = (float)floor(16.0 * pw);
    }

    const float2* x      = (const float2*)d_in[0];
    const float2* tables = (const float2*)d_in[1];
    float*        out    = (float*)d_out;

    hist_kernel<<<NPTS / HI_PER / THREADS, THREADS>>>((const float4*)x);
    scan_kernel<<<NSCANBLK, SCAN_BLK>>>();
    scatter_kernel<<<NPTS / SC_PER / THREADS, THREADS>>>(x);
    hashenc_kernel<<<NPTS / THREADS, THREADS>>>(tables, out, res);
}